// round 3
// baseline (speedup 1.0000x reference)
#include <cuda_runtime.h>
#include <cuda_fp16.h>
#include <cstdint>

// Problem constants
#define B_     2
#define N_IN_  163842
#define N_OUT_ 40962
#define C_     128
#define K_     7
#define C4_    (C_ / 4)    // 32 float4 per fp32 row
#define H2_    (C_ / 2)    // 64 half2 per fp16 row
#define SIGMA_ 0.4f

#define SCAN_T 1024
#define SCAN_PER ((N_OUT_ + SCAN_T - 1) / SCAN_T)   // 41

// Scratch (allocation-free rule: __device__ globals)
__device__ __align__(16) uint2 g_downh[(size_t)B_ * N_OUT_ * H2_ / 2]; // 21 MB fp16, pre-normalized
__device__ int g_count [N_OUT_];
__device__ int g_off   [N_OUT_];
__device__ int g_cursor[N_OUT_];
__device__ int g_child [N_IN_];

// ---------------------------------------------------------------------------
// CSR build step 1: zero histogram
// ---------------------------------------------------------------------------
__global__ void k_zero_counts() {
    int i = blockIdx.x * blockDim.x + threadIdx.x;
    if (i < N_OUT_) g_count[i] = 0;
}

// step 2: histogram of parent ids
__global__ void k_count(const int* __restrict__ parent) {
    int n = blockIdx.x * blockDim.x + threadIdx.x;
    if (n < N_IN_) atomicAdd(&g_count[parent[n]], 1);
}

// step 3: exclusive scan (single block, 1024 threads x 41 serial elems)
__global__ void k_scan() {
    __shared__ int s[SCAN_T];
    int t = threadIdx.x;
    int base = t * SCAN_PER;

    int tot = 0;
#pragma unroll
    for (int i = 0; i < SCAN_PER; i++) {
        int j = base + i;
        if (j < N_OUT_) tot += g_count[j];
    }
    s[t] = tot;
    __syncthreads();
    // inclusive Hillis-Steele
    for (int d = 1; d < SCAN_T; d <<= 1) {
        int v = (t >= d) ? s[t - d] : 0;
        __syncthreads();
        s[t] += v;
        __syncthreads();
    }
    int run = s[t] - tot;   // exclusive base for this thread's range
#pragma unroll
    for (int i = 0; i < SCAN_PER; i++) {
        int j = base + i;
        if (j < N_OUT_) {
            g_off[j] = run;
            g_cursor[j] = run;
            run += g_count[j];
        }
    }
}

// step 4: fill child lists
__global__ void k_fill(const int* __restrict__ parent) {
    int n = blockIdx.x * blockDim.x + threadIdx.x;
    if (n < N_IN_) {
        int p = parent[n];
        int pos = atomicAdd(&g_cursor[p], 1);
        g_child[pos] = n;
    }
}

// ---------------------------------------------------------------------------
// down_h[b,p,:] = ( sum_children omega_n * x[b,n,:] ) / max(sum omega, 1e-8)
// One warp per (p, b). Lane owns 4 channels (float4 of x, uint2 of fp16 out).
// grid = ceil(N_OUT*B/8), block = (32, 8)
// ---------------------------------------------------------------------------
__global__ void __launch_bounds__(256)
k_down(const float4* __restrict__ x,
       const float* __restrict__ omega) {
    int widx = blockIdx.x * blockDim.y + threadIdx.y;
    if (widx >= N_OUT_ * B_) return;
    int p = widx >> 1;
    int b = widx & 1;
    int lane = threadIdx.x;

    int off = g_off[p];
    int cnt = g_count[p];

    float4 acc = make_float4(0.f, 0.f, 0.f, 0.f);
    float dsum = 0.f;
    for (int i = 0; i < cnt; i++) {
        int n = g_child[off + i];                 // uniform across warp
        float om = __ldg(&omega[n]);              // broadcast
        float4 v = __ldg(&x[((size_t)b * N_IN_ + n) * C4_ + lane]);
        acc.x = fmaf(om, v.x, acc.x);
        acc.y = fmaf(om, v.y, acc.y);
        acc.z = fmaf(om, v.z, acc.z);
        acc.w = fmaf(om, v.w, acc.w);
        dsum += om;
    }
    float inv = 1.0f / fmaxf(dsum, 1e-8f);        // fold normalization in
    acc.x *= inv; acc.y *= inv; acc.z *= inv; acc.w *= inv;

    uint2 h;
    *(__half2*)&h.x = __floats2half2_rn(acc.x, acc.y);
    *(__half2*)&h.y = __floats2half2_rn(acc.z, acc.w);
    g_downh[((size_t)b * N_OUT_ + p) * (H2_ / 2) + lane] = h;
}

// ---------------------------------------------------------------------------
// out[b,n,:] = sum_k w_nk * down_h[b, cand_nk, :]   (down already normalized)
// One warp per (n, b): 7 independent 8B loads + 1 STG.128 row.
// grid = ceil(N_IN*B/8), block = (32, 8)
// ---------------------------------------------------------------------------
__global__ void __launch_bounds__(256)
k_gather(const float* __restrict__ delta,
         const float* __restrict__ mask,
         const int* __restrict__ cand,
         float4* __restrict__ out) {
    int widx = blockIdx.x * blockDim.y + threadIdx.y;
    if (widx >= N_IN_ * B_) return;
    int n = widx >> 1;
    int b = widx & 1;
    int lane = threadIdx.x;

    const float inv2s2 = 1.0f / (2.0f * SIGMA_ * SIGMA_);

    float e = 0.f;
    int   ci = 0;
    if (lane < K_) {
        float d = __ldg(&delta[n * K_ + lane]);
        float m = __ldg(&mask [n * K_ + lane]);
        e  = __expf(-d * d * inv2s2) * m;
        ci = __ldg(&cand[n * K_ + lane]);
    }

    // warp-sum of e (lanes >= K contribute 0)
    float s = e;
#pragma unroll
    for (int off = 16; off; off >>= 1)
        s += __shfl_xor_sync(0xffffffffu, s, off);

    float wp = e / fmaxf(s, 1e-8f);

    float wk [K_];
    int   idx[K_];
#pragma unroll
    for (int k = 0; k < K_; k++) {
        wk [k] = __shfl_sync(0xffffffffu, wp, k);
        idx[k] = __shfl_sync(0xffffffffu, ci, k);
    }

    // 7 independent 8-byte loads (MLP), then accumulate
    uint2 raw[K_];
#pragma unroll
    for (int k = 0; k < K_; k++)
        raw[k] = __ldg(&g_downh[((size_t)b * N_OUT_ + idx[k]) * (H2_ / 2) + lane]);

    float4 acc = make_float4(0.f, 0.f, 0.f, 0.f);
#pragma unroll
    for (int k = 0; k < K_; k++) {
        float2 lo = __half22float2(*(const __half2*)&raw[k].x);
        float2 hi = __half22float2(*(const __half2*)&raw[k].y);
        acc.x = fmaf(wk[k], lo.x, acc.x);
        acc.y = fmaf(wk[k], lo.y, acc.y);
        acc.z = fmaf(wk[k], hi.x, acc.z);
        acc.w = fmaf(wk[k], hi.y, acc.w);
    }
    out[((size_t)b * N_IN_ + n) * C4_ + lane] = acc;
}

// ---------------------------------------------------------------------------
// Harness entry. Inputs: x, omega, delta, cand_mask, parent_idx, cand_idx.
// Output: float32, (B, N_IN, C).
// ---------------------------------------------------------------------------
extern "C" void kernel_launch(void* const* d_in, const int* in_sizes, int n_in,
                              void* d_out, int out_size) {
    const float4* x      = (const float4*)d_in[0];
    const float*  omega  = (const float*) d_in[1];
    const float*  delta  = (const float*) d_in[2];
    const float*  cmask  = (const float*) d_in[3];
    const int*    parent = (const int*)   d_in[4];
    const int*    cand   = (const int*)   d_in[5];
    float4*       out    = (float4*)      d_out;

    k_zero_counts<<<(N_OUT_ + 255) / 256, 256>>>();
    k_count<<<(N_IN_ + 255) / 256, 256>>>(parent);
    k_scan<<<1, SCAN_T>>>();
    k_fill<<<(N_IN_ + 255) / 256, 256>>>(parent);

    dim3 bs(32, 8);
    int nbd = (N_OUT_ * B_ + 7) / 8;
    k_down<<<nbd, bs>>>(x, omega);

    int nbg = (N_IN_ * B_ + 7) / 8;
    k_gather<<<nbg, bs>>>(delta, cmask, cand, out);
}